// round 9
// baseline (speedup 1.0000x reference)
#include <cuda_runtime.h>
#include <cuda_fp16.h>
#include <cstdint>

// Fused QKV projection: X[16384,1024] @ [Wq|Wk|Wv][1024,3072] + bias,
// head-split epilogue. fp16 mma.sync.m16n8k16 (fp32 accum).
//
// R9: CUTLASS-style register double buffering. CTA 128x256, 8 warps of
// 64x64, BK=32, 4-stage cp.async (24KB/stage, 96KB). One CTA/SM, 255-reg
// budget. Fragments for chunk kc+1 (or next kt's kc=0, read from stage
// kt+1 which wait_group 1 guarantees resident) are loaded WHILE the
// current chunk's 32 MMAs issue, so LDS latency never gates the tensor pipe.

#define MDIM 16384
#define KDIM 1024
#define NTOT 3072
#define BM 128
#define BN 256
#define BK 32
#define NKT (KDIM / BK)          // 32
#define NSTAGE 4
#define A_BYTES 8192             // 8 mt x 2 kc x 512B
#define B_BYTES 16384            // 4 nbL x 2 kc x 4 c x 512B
#define STAGE_BYTES (A_BYTES + B_BYTES)       // 24576
#define SMEM_TOTAL (NSTAGE * STAGE_BYTES)     // 98304
#define OUT_PER_MAT (4 * 16 * 4096 * 64)

__device__ uint4 g_A[(size_t)1024 * 64 * 32];      // 32 MB
__device__ uint4 g_B[(size_t)48 * 64 * 4 * 32];    // 6 MB

__device__ __forceinline__ uint32_t h2u(float a, float b) {
    __half2 h = __float22half2_rn(make_float2(a, b));
    return *reinterpret_cast<uint32_t*>(&h);
}
__device__ __forceinline__ uint32_t smem_u32(const void* p) {
    uint32_t a;
    asm("{ .reg .u64 t; cvta.to.shared.u64 t, %1; cvt.u32.u64 %0, t; }" : "=r"(a) : "l"(p));
    return a;
}
__device__ __forceinline__ void cp16(uint32_t dst, const void* src) {
    asm volatile("cp.async.cg.shared.global [%0], [%1], 16;" :: "r"(dst), "l"(src));
}
__device__ __forceinline__ void mma_f16(float* c, const uint4& a, uint32_t b0, uint32_t b1) {
    asm volatile(
        "mma.sync.aligned.m16n8k16.row.col.f32.f16.f16.f32 "
        "{%0,%1,%2,%3},{%4,%5,%6,%7},{%8,%9},{%0,%1,%2,%3};"
        : "+f"(c[0]), "+f"(c[1]), "+f"(c[2]), "+f"(c[3])
        : "r"(a.x), "r"(a.y), "r"(a.z), "r"(a.w), "r"(b0), "r"(b1));
}

// ---------------- fused prep kernel (unchanged, proven) ----------------
__global__ void __launch_bounds__(256)
prep_ab(const float* __restrict__ X, const float* __restrict__ Wq,
        const float* __restrict__ Wk, const float* __restrict__ Wv) {
    const int lane = threadIdx.x & 31;
    const int g = lane >> 2, t = lane & 3;
    if (blockIdx.x < 8192) {
        const int tId = blockIdx.x * 8 + (threadIdx.x >> 5);   // 65536 tiles
        const int mt = tId >> 6, kt = tId & 63;
        const int r0 = mt * 16 + g;
        const int c0 = kt * 16 + 2 * t;
        const float2* x0 = reinterpret_cast<const float2*>(X + (size_t)r0 * KDIM + c0);
        const float2* x1 = reinterpret_cast<const float2*>(X + (size_t)(r0 + 8) * KDIM + c0);
        float2 v00 = x0[0], v02 = x0[4];
        float2 v10 = x1[0], v12 = x1[4];
        uint4 o;
        o.x = h2u(v00.x, v00.y);
        o.y = h2u(v10.x, v10.y);
        o.z = h2u(v02.x, v02.y);
        o.w = h2u(v12.x, v12.y);
        g_A[(size_t)tId * 32 + lane] = o;
    } else {
        const int wId = (blockIdx.x - 8192) * 8 + (threadIdx.x >> 5);   // 12288
        const int nb = wId >> 8;          // 0..47
        const int kk = (wId >> 2) & 63;   // ktile16
        const int c = wId & 3;            // chunk
        const int n0 = nb * 64 + (2 * c) * 8 + g;
        const int n1 = n0 + 8;
        const float* W = (n0 < 1024) ? Wq : (n0 < 2048) ? Wk : Wv;
        const int nc0 = n0 & 1023, nc1 = n1 & 1023;
        const int k0 = kk * 16 + 2 * t;
        uint4 o;
        o.x = h2u(W[(size_t)k0 * 1024 + nc0],       W[(size_t)(k0 + 1) * 1024 + nc0]);
        o.y = h2u(W[(size_t)(k0 + 8) * 1024 + nc0], W[(size_t)(k0 + 9) * 1024 + nc0]);
        o.z = h2u(W[(size_t)k0 * 1024 + nc1],       W[(size_t)(k0 + 1) * 1024 + nc1]);
        o.w = h2u(W[(size_t)(k0 + 8) * 1024 + nc1], W[(size_t)(k0 + 9) * 1024 + nc1]);
        g_B[((size_t)(nb * 64 + kk) * 4 + c) * 32 + lane] = o;
    }
}

// ---------------- GEMM ----------------
__global__ void __launch_bounds__(256, 1)
qkv_f16_mma(const float* __restrict__ bq, const float* __restrict__ bk,
            const float* __restrict__ bv, float* __restrict__ out) {
    extern __shared__ char smem[];
    const uint32_t sb = smem_u32(smem);
    const int tid = threadIdx.x;
    const int warp = tid >> 5;
    const int lane = tid & 31;
    const int g = lane >> 2, t = lane & 3;
    const int warpRow = warp >> 2;   // 0..1 (64 rows)
    const int warpCol = warp & 3;    // 0..3 (64 cols)

    const int nblk = blockIdx.x;         // 0..11
    const int mblk = blockIdx.y;         // 0..127
    const int mat = nblk >> 2;           // 0=q,1=k,2=v
    const int n0w = (nblk & 3) * BN;     // n within matrix
    const int m0 = mblk * BM;
    const int mtile0 = mblk * 8;
    const int nb0 = nblk * 4;            // global 64-col block index
    const float* bias = (mat == 0) ? bq : (mat == 1) ? bk : bv;

    float acc[4][8][4];
#pragma unroll
    for (int i = 0; i < 4; i++)
#pragma unroll
        for (int j = 0; j < 8; j++)
#pragma unroll
            for (int r = 0; r < 4; r++) acc[i][j][r] = 0.0f;

    // A smem/stage: [mt(8)][kc(2)][lane(32)] x 16B   (8KB)
    // B smem/stage: [nbL(4)][kc(2)][c(4)][lane(32)] x 16B  (16KB)
    auto load_stage = [&](int s, int kt) {
        const uint32_t aB = sb + s * STAGE_BYTES;
        const uint32_t bB = aB + A_BYTES;
#pragma unroll
        for (int i = 0; i < 2; i++) {   // A: 512 x 16B
            int chunk = tid + i * 256;
            int b = chunk >> 5, l = chunk & 31;
            int mt_i = b >> 1, kc = b & 1;
            cp16(aB + chunk * 16,
                 g_A + ((size_t)(mtile0 + mt_i) * 64 + kt * 2 + kc) * 32 + l);
        }
#pragma unroll
        for (int i = 0; i < 4; i++) {   // B: 1024 x 16B
            int chunk = tid + i * 256;
            int b = chunk >> 5, l = chunk & 31;
            int nbL = b >> 3, kc = (b >> 2) & 1, c = b & 3;
            cp16(bB + chunk * 16,
                 g_B + ((size_t)((nb0 + nbL) * 64 + kt * 2 + kc) * 4 + c) * 32 + l);
        }
        asm volatile("cp.async.commit_group;" ::: "memory");
    };

    // fragment loaders (lane-contiguous 16B -> conflict-free LDS.128)
    auto loadA = [&](uint4* af, const char* aP, int kc) {
#pragma unroll
        for (int mtl = 0; mtl < 4; mtl++)
            af[mtl] = *reinterpret_cast<const uint4*>(
                aP + (((warpRow * 4 + mtl) * 2 + kc) * 32 + lane) * 16);
    };
    auto loadB = [&](uint4* bf, const char* bP, int kc) {
#pragma unroll
        for (int c = 0; c < 4; c++)
            bf[c] = *reinterpret_cast<const uint4*>(
                bP + (((warpCol * 2 + kc) * 4 + c) * 32 + lane) * 16);
    };
    auto mma_block = [&](const uint4* af, const uint4* bf) {
#pragma unroll
        for (int c = 0; c < 4; c++)
#pragma unroll
            for (int mtl = 0; mtl < 4; mtl++) {
                mma_f16(acc[mtl][2 * c + 0], af[mtl], bf[c].x, bf[c].y);
                mma_f16(acc[mtl][2 * c + 1], af[mtl], bf[c].z, bf[c].w);
            }
    };

    load_stage(0, 0);
    load_stage(1, 1);
    load_stage(2, 2);
    asm volatile("cp.async.wait_group 2;" ::: "memory");
    __syncthreads();

    uint4 afc[4], bfc[4], afn[4], bfn[4];
    loadA(afc, smem, 0);
    loadB(bfc, smem + A_BYTES, 0);

    for (int kt = 0; kt < NKT; kt++) {
        const int s = kt & 3;
        const int sn = (kt + 1) & 3;

        // wait_group 1: all fills except the newest complete => slab kt+1
        // resident, so cross-boundary prefetch (below) is safe.
        asm volatile("cp.async.wait_group 1;" ::: "memory");
        __syncthreads();
        // Refill stage (kt+3)&3 (held slab kt-1; its last reads — bulk kc=1
        // at kt-1 and prefetch at kt-2 — happened before the barrier above).
        if (kt + 3 < NKT) load_stage((kt + 3) & 3, kt + 3);
        else asm volatile("cp.async.commit_group;" ::: "memory");

        const char* aP = smem + s * STAGE_BYTES;
        const char* bP = aP + A_BYTES;
        const char* aPn = smem + sn * STAGE_BYTES;
        const char* bPn = aPn + A_BYTES;

        // kc=0: prefetch kc=1 frags, then MMA on current frags
        loadA(afn, aP, 1);
        loadB(bfn, bP, 1);
        mma_block(afc, bfc);

        // kc=1: prefetch next kt's kc=0 frags (stage sn), then MMA
        loadA(afc, aPn, 0);   // at kt=31 reads stale slab 28 — unused
        loadB(bfc, bPn, 0);
        mma_block(afn, bfn);
    }
    asm volatile("cp.async.wait_group 0;" ::: "memory");

    // ---- epilogue: bias + head-split scatter ----
    float* outm = out + (size_t)mat * OUT_PER_MAT;
#pragma unroll
    for (int mtl = 0; mtl < 4; mtl++) {
#pragma unroll
        for (int rh = 0; rh < 2; rh++) {
            const int row = m0 + warpRow * 64 + mtl * 16 + g + rh * 8;
            const int bb = row >> 12;
            const int sq = row & 4095;
#pragma unroll
            for (int nt = 0; nt < 8; nt++) {
                const int nloc = n0w + warpCol * 64 + nt * 8 + 2 * t;
                const int head = nloc >> 6;
                const int d = nloc & 63;
                const float v0 = acc[mtl][nt][rh * 2 + 0] + bias[nloc];
                const float v1 = acc[mtl][nt][rh * 2 + 1] + bias[nloc + 1];
                const size_t idx = ((size_t)((bb * 16 + head) * 4096 + sq)) * 64 + d;
                *reinterpret_cast<float2*>(outm + idx) = make_float2(v0, v1);
            }
        }
    }
}

// ---------------- launch ----------------
extern "C" void kernel_launch(void* const* d_in, const int* in_sizes, int n_in,
                              void* d_out, int out_size) {
    const float* X  = (const float*)d_in[0];
    const float* Wq = (const float*)d_in[1];
    const float* bq = (const float*)d_in[2];
    const float* Wk = (const float*)d_in[3];
    const float* bk = (const float*)d_in[4];
    const float* Wv = (const float*)d_in[5];
    const float* bv = (const float*)d_in[6];
    float* out = (float*)d_out;

    prep_ab<<<8192 + 1536, 256>>>(X, Wq, Wk, Wv);

    cudaFuncSetAttribute(qkv_f16_mma,
                         cudaFuncAttributeMaxDynamicSharedMemorySize, SMEM_TOTAL);
    qkv_f16_mma<<<dim3(12, 128), 256, SMEM_TOTAL>>>(bq, bk, bv, out);
}

// round 10
// speedup vs baseline: 1.1103x; 1.1103x over previous
#include <cuda_runtime.h>
#include <cuda_fp16.h>
#include <cstdint>

// Fused QKV projection: X[16384,1024] @ [Wq|Wk|Wv][1024,3072] + bias,
// head-split epilogue. fp16 mma.sync.m16n8k16 (fp32 accum).
//
// R10: warp-autonomous pipelines. Each warp cp.asyncs EXACTLY the lane-
// private fragment data it later consumes (lane l copies slot ..*32+l and
// reads the same slot), so cp.async.wait_group alone provides visibility
// and there are NO __syncthreads in the K-loop. 4 warps of 64x64 per
// 128x128 CTA, per-warp 2-stage x 8KB private smem, 3 CTAs/SM (12 warps).
// A/B fetched twice per CTA (pair-warps no longer share smem): L2 traffic
// 2x, which R7's L2=23.8% says we can afford.

#define MDIM 16384
#define KDIM 1024
#define NTOT 3072
#define BM 128
#define BN 128
#define BK 32
#define NKT (KDIM / BK)          // 32
#define WSTAGE_BYTES 8192        // per-warp stage: A 4KB + B 4KB
#define SMEM_TOTAL (4 * 2 * WSTAGE_BYTES)   // 65536 per CTA
#define OUT_PER_MAT (4 * 16 * 4096 * 64)

__device__ uint4 g_A[(size_t)1024 * 64 * 32];      // 32 MB
__device__ uint4 g_B[(size_t)48 * 64 * 4 * 32];    // 6 MB

__device__ __forceinline__ uint32_t h2u(float a, float b) {
    __half2 h = __float22half2_rn(make_float2(a, b));
    return *reinterpret_cast<uint32_t*>(&h);
}
__device__ __forceinline__ uint32_t smem_u32(const void* p) {
    uint32_t a;
    asm("{ .reg .u64 t; cvta.to.shared.u64 t, %1; cvt.u32.u64 %0, t; }" : "=r"(a) : "l"(p));
    return a;
}
__device__ __forceinline__ void cp16(uint32_t dst, const void* src) {
    asm volatile("cp.async.cg.shared.global [%0], [%1], 16;" :: "r"(dst), "l"(src));
}
__device__ __forceinline__ void mma_f16(float* c, const uint4& a, uint32_t b0, uint32_t b1) {
    asm volatile(
        "mma.sync.aligned.m16n8k16.row.col.f32.f16.f16.f32 "
        "{%0,%1,%2,%3},{%4,%5,%6,%7},{%8,%9},{%0,%1,%2,%3};"
        : "+f"(c[0]), "+f"(c[1]), "+f"(c[2]), "+f"(c[3])
        : "r"(a.x), "r"(a.y), "r"(a.z), "r"(a.w), "r"(b0), "r"(b1));
}

// ---------------- fused prep kernel (proven) ----------------
// blocks [0,8192): A fragments.  blocks [8192,9728): B fragments.
__global__ void __launch_bounds__(256)
prep_ab(const float* __restrict__ X, const float* __restrict__ Wq,
        const float* __restrict__ Wk, const float* __restrict__ Wv) {
    const int lane = threadIdx.x & 31;
    const int g = lane >> 2, t = lane & 3;
    if (blockIdx.x < 8192) {
        const int tId = blockIdx.x * 8 + (threadIdx.x >> 5);   // 65536 tiles
        const int mt = tId >> 6, kt = tId & 63;
        const int r0 = mt * 16 + g;
        const int c0 = kt * 16 + 2 * t;
        const float2* x0 = reinterpret_cast<const float2*>(X + (size_t)r0 * KDIM + c0);
        const float2* x1 = reinterpret_cast<const float2*>(X + (size_t)(r0 + 8) * KDIM + c0);
        float2 v00 = x0[0], v02 = x0[4];
        float2 v10 = x1[0], v12 = x1[4];
        uint4 o;
        o.x = h2u(v00.x, v00.y);
        o.y = h2u(v10.x, v10.y);
        o.z = h2u(v02.x, v02.y);
        o.w = h2u(v12.x, v12.y);
        g_A[(size_t)tId * 32 + lane] = o;
    } else {
        const int wId = (blockIdx.x - 8192) * 8 + (threadIdx.x >> 5);   // 12288
        const int nb = wId >> 8;          // 0..47
        const int kk = (wId >> 2) & 63;   // ktile16
        const int c = wId & 3;            // chunk
        const int n0 = nb * 64 + (2 * c) * 8 + g;
        const int n1 = n0 + 8;
        const float* W = (n0 < 1024) ? Wq : (n0 < 2048) ? Wk : Wv;
        const int nc0 = n0 & 1023, nc1 = n1 & 1023;
        const int k0 = kk * 16 + 2 * t;
        uint4 o;
        o.x = h2u(W[(size_t)k0 * 1024 + nc0],       W[(size_t)(k0 + 1) * 1024 + nc0]);
        o.y = h2u(W[(size_t)(k0 + 8) * 1024 + nc0], W[(size_t)(k0 + 9) * 1024 + nc0]);
        o.z = h2u(W[(size_t)k0 * 1024 + nc1],       W[(size_t)(k0 + 1) * 1024 + nc1]);
        o.w = h2u(W[(size_t)(k0 + 8) * 1024 + nc1], W[(size_t)(k0 + 9) * 1024 + nc1]);
        g_B[((size_t)(nb * 64 + kk) * 4 + c) * 32 + lane] = o;
    }
}

// ---------------- GEMM ----------------
__global__ void __launch_bounds__(128, 3)
qkv_f16_mma(const float* __restrict__ bq, const float* __restrict__ bk,
            const float* __restrict__ bv, float* __restrict__ out) {
    extern __shared__ char smem[];
    const uint32_t sb = smem_u32(smem);
    const int tid = threadIdx.x;
    const int warp = tid >> 5;
    const int lane = tid & 31;
    const int g = lane >> 2, t = lane & 3;
    const int warpRow = warp >> 1;   // 0..1 (64 rows)
    const int warpCol = warp & 1;    // 0..1 (64 cols)

    const int nblk = blockIdx.x;         // 0..23
    const int mblk = blockIdx.y;         // 0..127
    const int mat = nblk >> 3;
    const int n0w = (nblk & 7) * BN;     // n within matrix
    const int m0 = mblk * BM;
    const float* bias = (mat == 0) ? bq : (mat == 1) ? bk : bv;

    // this warp's private gmem slices (fragment order)
    const int mtileW = mblk * 8 + warpRow * 4;       // 4 mtiles of A
    const int nbW = nblk * 2 + warpCol;              // one 64-col B block

    float acc[4][8][4];
#pragma unroll
    for (int i = 0; i < 4; i++)
#pragma unroll
        for (int j = 0; j < 8; j++)
#pragma unroll
            for (int r = 0; r < 4; r++) acc[i][j][r] = 0.0f;

    // per-warp smem: [warp][stage]{ A: (mtl*2+kc)*512+lane*16 | B(+4KB): (kc*4+c)*512+lane*16 }
    const uint32_t wbase = sb + warp * 2 * WSTAGE_BYTES;

    // lane-private fill: lane l copies exactly the 16B slots it will LDS.
    auto fill_stage = [&](int s, int kt) {
        const uint32_t stb = wbase + s * WSTAGE_BYTES;
#pragma unroll
        for (int mtl = 0; mtl < 4; mtl++)
#pragma unroll
            for (int kc = 0; kc < 2; kc++)
                cp16(stb + (uint32_t)((mtl * 2 + kc) * 32 + lane) * 16,
                     g_A + ((size_t)(mtileW + mtl) * 64 + kt * 2 + kc) * 32 + lane);
#pragma unroll
        for (int kc = 0; kc < 2; kc++)
#pragma unroll
            for (int c = 0; c < 4; c++)
                cp16(stb + 4096 + (uint32_t)((kc * 4 + c) * 32 + lane) * 16,
                     g_B + ((size_t)(nbW * 64 + kt * 2 + kc) * 4 + c) * 32 + lane);
        asm volatile("cp.async.commit_group;" ::: "memory");
    };

    fill_stage(0, 0);
    fill_stage(1, 1);

    for (int kt = 0; kt < NKT; kt++) {
        const int s = kt & 1;
        // Wait until only the newest group is pending -> stage s (group kt)
        // complete. Lane-private data: no __syncthreads needed.
        asm volatile("cp.async.wait_group 1;" ::: "memory");

        const char* aP = smem + (warp * 2 + s) * WSTAGE_BYTES;
        const char* bP = aP + 4096;
#pragma unroll
        for (int kc = 0; kc < 2; kc++) {
            uint4 af[4];
#pragma unroll
            for (int mtl = 0; mtl < 4; mtl++)
                af[mtl] = *reinterpret_cast<const uint4*>(
                    aP + ((mtl * 2 + kc) * 32 + lane) * 16);
#pragma unroll
            for (int c = 0; c < 4; c++) {
                uint4 b = *reinterpret_cast<const uint4*>(
                    bP + ((kc * 4 + c) * 32 + lane) * 16);
#pragma unroll
                for (int mtl = 0; mtl < 4; mtl++) {
                    mma_f16(acc[mtl][2 * c + 0], af[mtl], b.x, b.y);
                    mma_f16(acc[mtl][2 * c + 1], af[mtl], b.z, b.w);
                }
            }
        }
        // Refill stage s with slab kt+2. All LDS reads of stage s were issued
        // above (same thread, program order), so the overwrite cannot race.
        if (kt + 2 < NKT) fill_stage(s, kt + 2);
        else asm volatile("cp.async.commit_group;" ::: "memory");
    }
    asm volatile("cp.async.wait_group 0;" ::: "memory");

    // ---- epilogue: bias + head-split scatter ----
    float* outm = out + (size_t)mat * OUT_PER_MAT;
#pragma unroll
    for (int mtl = 0; mtl < 4; mtl++) {
#pragma unroll
        for (int rh = 0; rh < 2; rh++) {
            const int row = m0 + warpRow * 64 + mtl * 16 + g + rh * 8;
            const int bb = row >> 12;
            const int sq = row & 4095;
#pragma unroll
            for (int nt = 0; nt < 8; nt++) {
                const int nloc = n0w + warpCol * 64 + nt * 8 + 2 * t;
                const int head = nloc >> 6;
                const int d = nloc & 63;
                const float v0 = acc[mtl][nt][rh * 2 + 0] + bias[nloc];
                const float v1 = acc[mtl][nt][rh * 2 + 1] + bias[nloc + 1];
                const size_t idx = ((size_t)((bb * 16 + head) * 4096 + sq)) * 64 + d;
                *reinterpret_cast<float2*>(outm + idx) = make_float2(v0, v1);
            }
        }
    }
}

// ---------------- launch ----------------
extern "C" void kernel_launch(void* const* d_in, const int* in_sizes, int n_in,
                              void* d_out, int out_size) {
    const float* X  = (const float*)d_in[0];
    const float* Wq = (const float*)d_in[1];
    const float* bq = (const float*)d_in[2];
    const float* Wk = (const float*)d_in[3];
    const float* bk = (const float*)d_in[4];
    const float* Wv = (const float*)d_in[5];
    const float* bv = (const float*)d_in[6];
    float* out = (float*)d_out;

    prep_ab<<<8192 + 1536, 256>>>(X, Wq, Wk, Wv);

    cudaFuncSetAttribute(qkv_f16_mma,
                         cudaFuncAttributeMaxDynamicSharedMemorySize, SMEM_TOTAL);
    qkv_f16_mma<<<dim3(24, 128), 128, SMEM_TOTAL>>>(bq, bk, bv, out);
}

// round 11
// speedup vs baseline: 1.5742x; 1.4178x over previous
#include <cuda_runtime.h>
#include <cuda_fp16.h>
#include <cstdint>

// Fused QKV projection: X[16384,1024] @ [Wq|Wk|Wv][1024,3072] + bias,
// head-split epilogue. fp16 mma.sync.m16n8k16 (fp32 accum).
//
// R11 = R6 (best: 272.5us) with one change: the next-stage cp.async fill is
// issued BETWEEN the kc=0 and kc=1 MMA blocks instead of immediately after
// the barrier. The barrier already guarantees all warps consumed stage kt-1,
// so the refill stays race-free, but the ~64 issue-cycles of LDGSTS no
// longer sit between the barrier and the first HMMA of the iteration.
// GEMM: CTA 128x128, 4 warps (2x2 of 64x64), BK=32, 4-stage, 3 CTAs/SM.

#define MDIM 16384
#define KDIM 1024
#define NTOT 3072
#define BM 128
#define BN 128
#define BK 32
#define NKT (KDIM / BK)          // 32
#define NSTAGE 4
#define A_BYTES 8192             // 8 mt x 2 kc x 512B
#define B_BYTES 8192             // 2 nbL x 2 kc x 4 c x 512B
#define STAGE_BYTES (A_BYTES + B_BYTES)       // 16384
#define SMEM_TOTAL (NSTAGE * STAGE_BYTES)     // 65536
#define OUT_PER_MAT (4 * 16 * 4096 * 64)

__device__ uint4 g_A[(size_t)1024 * 64 * 32];      // 32 MB
__device__ uint4 g_B[(size_t)48 * 64 * 4 * 32];    // 6 MB

__device__ __forceinline__ uint32_t h2u(float a, float b) {
    __half2 h = __float22half2_rn(make_float2(a, b));
    return *reinterpret_cast<uint32_t*>(&h);
}
__device__ __forceinline__ uint32_t smem_u32(const void* p) {
    uint32_t a;
    asm("{ .reg .u64 t; cvta.to.shared.u64 t, %1; cvt.u32.u64 %0, t; }" : "=r"(a) : "l"(p));
    return a;
}
__device__ __forceinline__ void cp16(uint32_t dst, const void* src) {
    asm volatile("cp.async.cg.shared.global [%0], [%1], 16;" :: "r"(dst), "l"(src));
}
__device__ __forceinline__ void mma_f16(float* c, const uint4& a, uint32_t b0, uint32_t b1) {
    asm volatile(
        "mma.sync.aligned.m16n8k16.row.col.f32.f16.f16.f32 "
        "{%0,%1,%2,%3},{%4,%5,%6,%7},{%8,%9},{%0,%1,%2,%3};"
        : "+f"(c[0]), "+f"(c[1]), "+f"(c[2]), "+f"(c[3])
        : "r"(a.x), "r"(a.y), "r"(a.z), "r"(a.w), "r"(b0), "r"(b1));
}

// ---------------- prep kernels (proven) ----------------
// A fragment (m16n8k16, row-major A 16x16), lane (g,t):
//   a0={A[g][2t],A[g][2t+1]} a1={A[g+8][..]} a2={A[g][2t+8],..} a3={A[g+8][2t+8],..}
__global__ void __launch_bounds__(256) prep_a(const float* __restrict__ X) {
    const int tId = blockIdx.x * 8 + (threadIdx.x >> 5);   // 65536 tiles
    const int lane = threadIdx.x & 31;
    const int g = lane >> 2, t = lane & 3;
    const int mt = tId >> 6, kt = tId & 63;
    const int r0 = mt * 16 + g;
    const int c0 = kt * 16 + 2 * t;
    const float2* x0 = reinterpret_cast<const float2*>(X + (size_t)r0 * KDIM + c0);
    const float2* x1 = reinterpret_cast<const float2*>(X + (size_t)(r0 + 8) * KDIM + c0);
    float2 v00 = x0[0], v02 = x0[4];
    float2 v10 = x1[0], v12 = x1[4];
    uint4 o;
    o.x = h2u(v00.x, v00.y);
    o.y = h2u(v10.x, v10.y);
    o.z = h2u(v02.x, v02.y);
    o.w = h2u(v12.x, v12.y);
    g_A[(size_t)tId * 32 + lane] = o;
}

// B fragment (k16 x n8 "col"), lane (g,t):
//   b0={B[2t][g],B[2t+1][g]}  b1={B[2t+8][g],B[2t+9][g]}; chunk c packs ntiles 2c,2c+1.
__global__ void __launch_bounds__(256) prep_b(const float* __restrict__ Wq,
                                              const float* __restrict__ Wk,
                                              const float* __restrict__ Wv) {
    const int wId = blockIdx.x * 8 + (threadIdx.x >> 5);   // 12288 warps
    const int lane = threadIdx.x & 31;
    const int g = lane >> 2, t = lane & 3;
    const int nb = wId >> 8;          // 0..47
    const int kk = (wId >> 2) & 63;   // ktile16
    const int c = wId & 3;            // chunk
    const int n0 = nb * 64 + (2 * c) * 8 + g;
    const int n1 = n0 + 8;
    const float* W = (n0 < 1024) ? Wq : (n0 < 2048) ? Wk : Wv;
    const int nc0 = n0 & 1023, nc1 = n1 & 1023;
    const int k0 = kk * 16 + 2 * t;
    uint4 o;
    o.x = h2u(W[(size_t)k0 * 1024 + nc0],       W[(size_t)(k0 + 1) * 1024 + nc0]);
    o.y = h2u(W[(size_t)(k0 + 8) * 1024 + nc0], W[(size_t)(k0 + 9) * 1024 + nc0]);
    o.z = h2u(W[(size_t)k0 * 1024 + nc1],       W[(size_t)(k0 + 1) * 1024 + nc1]);
    o.w = h2u(W[(size_t)(k0 + 8) * 1024 + nc1], W[(size_t)(k0 + 9) * 1024 + nc1]);
    g_B[((size_t)(nb * 64 + kk) * 4 + c) * 32 + lane] = o;
}

// ---------------- GEMM ----------------
__global__ void __launch_bounds__(128, 3)
qkv_f16_mma(const float* __restrict__ bq, const float* __restrict__ bk,
            const float* __restrict__ bv, float* __restrict__ out) {
    extern __shared__ char smem[];
    const uint32_t sb = smem_u32(smem);
    const int tid = threadIdx.x;
    const int warp = tid >> 5;
    const int lane = tid & 31;
    const int g = lane >> 2, t = lane & 3;
    const int warpRow = warp >> 1;   // 0..1 (64 rows)
    const int warpCol = warp & 1;    // 0..1 (64 cols)

    const int nblk = blockIdx.x;         // 0..23
    const int mblk = blockIdx.y;         // 0..127
    const int mat = nblk >> 3;
    const int n0w = (nblk & 7) * BN;     // n within matrix
    const int m0 = mblk * BM;
    const int mtile0 = mblk * 8;
    const int nb0 = nblk * 2;            // global 64-col block index
    const float* bias = (mat == 0) ? bq : (mat == 1) ? bk : bv;

    float acc[4][8][4];
#pragma unroll
    for (int i = 0; i < 4; i++)
#pragma unroll
        for (int j = 0; j < 8; j++)
#pragma unroll
            for (int r = 0; r < 4; r++) acc[i][j][r] = 0.0f;

    // A smem: [mt(8)][kc(2)][lane(32)] x 16B
    // B smem: [nbL(2)][kc(2)][c(4)][lane(32)] x 16B
    auto load_stage = [&](int s, int kt) {
        const uint32_t aB = sb + s * STAGE_BYTES;
        const uint32_t bB = aB + A_BYTES;
#pragma unroll
        for (int i = 0; i < 4; i++) {   // A: 512 x 16B
            int chunk = tid + i * 128;
            int b = chunk >> 5, l = chunk & 31;
            int mt_i = b >> 1, kc = b & 1;
            cp16(aB + chunk * 16,
                 g_A + ((size_t)(mtile0 + mt_i) * 64 + kt * 2 + kc) * 32 + l);
        }
#pragma unroll
        for (int i = 0; i < 4; i++) {   // B: 512 x 16B
            int chunk = tid + i * 128;
            int b = chunk >> 5, l = chunk & 31;
            int nbL = b >> 3, kc = (b >> 2) & 1, c = b & 3;
            cp16(bB + chunk * 16,
                 g_B + ((size_t)((nb0 + nbL) * 64 + kt * 2 + kc) * 4 + c) * 32 + l);
        }
        asm volatile("cp.async.commit_group;" ::: "memory");
    };

    load_stage(0, 0);
    load_stage(1, 1);
    load_stage(2, 2);

    for (int kt = 0; kt < NKT; kt++) {
        const int s = kt & 3;
        asm volatile("cp.async.wait_group 2;" ::: "memory");
        __syncthreads();

        const char* aP = smem + s * STAGE_BYTES;
        const char* bP = aP + A_BYTES;

        // ---- kc = 0: straight to tensor work after the barrier ----
        {
            uint4 af[4];
#pragma unroll
            for (int mtl = 0; mtl < 4; mtl++)
                af[mtl] = *reinterpret_cast<const uint4*>(
                    aP + (((warpRow * 4 + mtl) * 2 + 0) * 32 + lane) * 16);
#pragma unroll
            for (int c = 0; c < 4; c++) {
                uint4 b = *reinterpret_cast<const uint4*>(
                    bP + (((warpCol * 2 + 0) * 4 + c) * 32 + lane) * 16);
#pragma unroll
                for (int mtl = 0; mtl < 4; mtl++) {
                    mma_f16(acc[mtl][2 * c + 0], af[mtl], b.x, b.y);
                    mma_f16(acc[mtl][2 * c + 1], af[mtl], b.z, b.w);
                }
            }
        }

        // ---- refill stage (kt+3)&3 here, hidden under the MMA stream.
        // Safe: the barrier above proves all warps finished reading its old
        // contents (stage kt-1) during iteration kt-1.
        if (kt + 3 < NKT) load_stage((kt + 3) & 3, kt + 3);

        // ---- kc = 1 ----
        {
            uint4 af[4];
#pragma unroll
            for (int mtl = 0; mtl < 4; mtl++)
                af[mtl] = *reinterpret_cast<const uint4*>(
                    aP + (((warpRow * 4 + mtl) * 2 + 1) * 32 + lane) * 16);
#pragma unroll
            for (int c = 0; c < 4; c++) {
                uint4 b = *reinterpret_cast<const uint4*>(
                    bP + (((warpCol * 2 + 1) * 4 + c) * 32 + lane) * 16);
#pragma unroll
                for (int mtl = 0; mtl < 4; mtl++) {
                    mma_f16(acc[mtl][2 * c + 0], af[mtl], b.x, b.y);
                    mma_f16(acc[mtl][2 * c + 1], af[mtl], b.z, b.w);
                }
            }
        }
    }
    asm volatile("cp.async.wait_group 0;" ::: "memory");

    // ---- epilogue: bias + head-split scatter ----
    float* outm = out + (size_t)mat * OUT_PER_MAT;
#pragma unroll
    for (int mtl = 0; mtl < 4; mtl++) {
#pragma unroll
        for (int rh = 0; rh < 2; rh++) {
            const int row = m0 + warpRow * 64 + mtl * 16 + g + rh * 8;
            const int bb = row >> 12;
            const int sq = row & 4095;
#pragma unroll
            for (int nt = 0; nt < 8; nt++) {
                const int nloc = n0w + warpCol * 64 + nt * 8 + 2 * t;
                const int head = nloc >> 6;
                const int d = nloc & 63;
                const float v0 = acc[mtl][nt][rh * 2 + 0] + bias[nloc];
                const float v1 = acc[mtl][nt][rh * 2 + 1] + bias[nloc + 1];
                const size_t idx = ((size_t)((bb * 16 + head) * 4096 + sq)) * 64 + d;
                *reinterpret_cast<float2*>(outm + idx) = make_float2(v0, v1);
            }
        }
    }
}

// ---------------- launch ----------------
extern "C" void kernel_launch(void* const* d_in, const int* in_sizes, int n_in,
                              void* d_out, int out_size) {
    const float* X  = (const float*)d_in[0];
    const float* Wq = (const float*)d_in[1];
    const float* bq = (const float*)d_in[2];
    const float* Wk = (const float*)d_in[3];
    const float* bk = (const float*)d_in[4];
    const float* Wv = (const float*)d_in[5];
    const float* bv = (const float*)d_in[6];
    float* out = (float*)d_out;

    prep_a<<<8192, 256>>>(X);
    prep_b<<<1536, 256>>>(Wq, Wk, Wv);

    cudaFuncSetAttribute(qkv_f16_mma,
                         cudaFuncAttributeMaxDynamicSharedMemorySize, SMEM_TOTAL);
    qkv_f16_mma<<<dim3(24, 128), 128, SMEM_TOTAL>>>(bq, bk, bv, out);
}